// round 1
// baseline (speedup 1.0000x reference)
#include <cuda_runtime.h>
#include <cuda_bf16.h>

// Problem constants (fixed-shape problem; runtime values derived from in_sizes)
#define NMAX 100000
#define EMAX 1600000

// Scratch (device globals are zero-initialized at module load; kernels below
// maintain the zero invariant for g_agg4 / g_deg across graph replays).
__device__ float4 g_self4[NMAX * 8];   // self-path projections  [N,32]
__device__ float4 g_proj4[NMAX * 8];   // neighbor-path projections [N,32]
__device__ float4 g_agg4[NMAX * 8];    // scatter-sum accumulator [N,32]
__device__ float  g_inv[NMAX];         // 1/max(deg,1)
__device__ unsigned int g_deg[NMAX];
__device__ int    g_is32;              // edge_index dtype flag

// ---------------------------------------------------------------------------
// Detect whether edge_index is int32 or int64 (JAX may downcast silently).
// If interpreted as int64 and any of the first 64 values is out of [0,n),
// the data must be int32 (a random int32 pair gives value >= 2^32 w.h.p.).
// ---------------------------------------------------------------------------
__global__ void detect_kernel(const long long* __restrict__ ei, int n, int e) {
    if (blockIdx.x == 0 && threadIdx.x == 0) {
        int is32 = 0;
        int m = e < 64 ? e : 64;
        for (int i = 0; i < m; i++) {
            long long v = ei[i];
            if (v < 0 || v >= (long long)n) { is32 = 1; break; }
        }
        g_is32 = is32;
    }
}

__device__ __forceinline__ long long load_idx(const void* ei, long long elem) {
    if (g_is32) return (long long)((const int*)ei)[elem];
    return ((const long long*)ei)[elem];
}

// ---------------------------------------------------------------------------
// proj1: g_self = x @ W_self1 + b_self1 ; g_proj = x @ W_neigh1
// warp-per-node, weights in SMEM, x row held in 2 regs + shfl broadcast.
// ---------------------------------------------------------------------------
__global__ void proj1_kernel(const float* __restrict__ x,
                             const float* __restrict__ Ws,
                             const float* __restrict__ bs,
                             const float* __restrict__ Wn, int n) {
    __shared__ float sWs[64 * 32], sWn[64 * 32], sbs[32];
    for (int i = threadIdx.x; i < 64 * 32; i += 256) { sWs[i] = Ws[i]; sWn[i] = Wn[i]; }
    if (threadIdx.x < 32) sbs[threadIdx.x] = bs[threadIdx.x];
    __syncthreads();

    int warp = threadIdx.x >> 5, lane = threadIdx.x & 31;
    int node = blockIdx.x * 8 + warp;
    if (node >= n) return;

    float xv0 = x[(size_t)node * 64 + lane];
    float xv1 = x[(size_t)node * 64 + 32 + lane];
    float accs = sbs[lane], accn = 0.f;
#pragma unroll
    for (int k = 0; k < 32; k++) {
        float xk = __shfl_sync(0xffffffffu, xv0, k);
        accs = fmaf(xk, sWs[k * 32 + lane], accs);
        accn = fmaf(xk, sWn[k * 32 + lane], accn);
    }
#pragma unroll
    for (int k = 0; k < 32; k++) {
        float xk = __shfl_sync(0xffffffffu, xv1, k);
        accs = fmaf(xk, sWs[(32 + k) * 32 + lane], accs);
        accn = fmaf(xk, sWn[(32 + k) * 32 + lane], accn);
    }
    ((float*)g_self4)[(size_t)node * 32 + lane] = accs;
    ((float*)g_proj4)[(size_t)node * 32 + lane] = accn;
}

// ---------------------------------------------------------------------------
// scatter: g_agg[dst] += g_proj[src] via red.global.add.v4.f32.
// 8 threads per edge (each handles one float4). COUNT also bumps degree.
// ---------------------------------------------------------------------------
template <bool COUNT>
__global__ void scatter_kernel(const void* __restrict__ ei, int e) {
    int gid = blockIdx.x * blockDim.x + threadIdx.x;
    int edge = gid >> 3;
    if (edge >= e) return;
    int part = gid & 7;

    long long s = load_idx(ei, edge);            // src = edge_index[0][edge]
    long long d = load_idx(ei, (long long)e + edge);  // dst = edge_index[1][edge]

    float4 v = g_proj4[s * 8 + part];
    float4* addr = &g_agg4[d * 8 + part];
    asm volatile("red.global.add.v4.f32 [%0], {%1, %2, %3, %4};"
                 :: "l"(addr), "f"(v.x), "f"(v.y), "f"(v.z), "f"(v.w)
                 : "memory");
    if (COUNT && part == 0) atomicAdd(&g_deg[d], 1u);
}

// ---------------------------------------------------------------------------
// inv: g_inv = 1/max(deg,1); reset deg to keep the replay invariant.
// ---------------------------------------------------------------------------
__global__ void inv_kernel(int n) {
    int i = blockIdx.x * blockDim.x + threadIdx.x;
    if (i < n) {
        unsigned c = g_deg[i];
        g_inv[i] = 1.0f / (float)(c > 1u ? c : 1u);
        g_deg[i] = 0u;
    }
}

// ---------------------------------------------------------------------------
// combine1: h1 = relu(agg*inv + b_neigh1 + self); then project for layer 2:
//   g_self = h1 @ W_self2 + b_self2 ; g_proj = h1 @ W_neigh2.
// Re-zeroes g_agg for the next scatter.
// ---------------------------------------------------------------------------
__global__ void combine1_kernel(const float* __restrict__ Ws2,
                                const float* __restrict__ bs2,
                                const float* __restrict__ Wn2,
                                const float* __restrict__ bn1, int n) {
    __shared__ float sWs[32 * 32], sWn[32 * 32], sbs[32], sbn[32];
    for (int i = threadIdx.x; i < 1024; i += 256) { sWs[i] = Ws2[i]; sWn[i] = Wn2[i]; }
    if (threadIdx.x < 32) { sbs[threadIdx.x] = bs2[threadIdx.x]; sbn[threadIdx.x] = bn1[threadIdx.x]; }
    __syncthreads();

    int warp = threadIdx.x >> 5, lane = threadIdx.x & 31;
    int node = blockIdx.x * 8 + warp;
    if (node >= n) return;

    float* ga = (float*)g_agg4;
    float* gs = (float*)g_self4;
    float* gp = (float*)g_proj4;
    size_t off = (size_t)node * 32 + lane;

    float a = ga[off];
    ga[off] = 0.f;
    float inv = g_inv[node];
    float h = fmaxf(fmaf(a, inv, sbn[lane] + gs[off]), 0.f);

    float accs = sbs[lane], accn = 0.f;
#pragma unroll
    for (int k = 0; k < 32; k++) {
        float hk = __shfl_sync(0xffffffffu, h, k);
        accs = fmaf(hk, sWs[k * 32 + lane], accs);
        accn = fmaf(hk, sWn[k * 32 + lane], accn);
    }
    gs[off] = accs;
    gp[off] = accn;
}

// ---------------------------------------------------------------------------
// combine2: h2 = relu(agg*inv + b_neigh2 + self); write x32 = h2 and
// logits = h2 @ W_out + b_out. Re-zeroes g_agg for the next replay.
// ---------------------------------------------------------------------------
__global__ void combine2_kernel(const float* __restrict__ Wout,
                                const float* __restrict__ bout,
                                const float* __restrict__ bn2, int n,
                                float* __restrict__ out_x32,
                                float* __restrict__ out_logits) {
    __shared__ float sW[32 * 40], sb[40], sbn[32];
    for (int i = threadIdx.x; i < 1280; i += 256) sW[i] = Wout[i];
    if (threadIdx.x < 40) sb[threadIdx.x] = bout[threadIdx.x];
    if (threadIdx.x < 32) sbn[threadIdx.x] = bn2[threadIdx.x];
    __syncthreads();

    int warp = threadIdx.x >> 5, lane = threadIdx.x & 31;
    int node = blockIdx.x * 8 + warp;
    if (node >= n) return;

    float* ga = (float*)g_agg4;
    float* gs = (float*)g_self4;
    size_t off = (size_t)node * 32 + lane;

    float a = ga[off];
    ga[off] = 0.f;
    float inv = g_inv[node];
    float h = fmaxf(fmaf(a, inv, sbn[lane] + gs[off]), 0.f);
    out_x32[off] = h;

    float acc0 = sb[lane];
    float acc1 = (lane < 8) ? sb[32 + lane] : 0.f;
#pragma unroll
    for (int k = 0; k < 32; k++) {
        float hk = __shfl_sync(0xffffffffu, h, k);
        acc0 = fmaf(hk, sW[k * 40 + lane], acc0);
        acc1 = fmaf(hk, sW[k * 40 + 32 + (lane & 7)], acc1);  // lane&7 keeps in bounds; result only used when lane<8
    }
    out_logits[(size_t)node * 40 + lane] = acc0;
    if (lane < 8) out_logits[(size_t)node * 40 + 32 + lane] = acc1;
}

// ---------------------------------------------------------------------------
// Launch. Inputs (metadata order): x, edge_index, W_self1, b_self1, W_neigh1,
// b_neigh1, W_self2, b_self2, W_neigh2, b_neigh2, W_out, b_out, W_lin1, b_lin1.
// Output: concat(x32 [N,32], logits [N,40]) as float32. W_lin1 path is dead.
// ---------------------------------------------------------------------------
extern "C" void kernel_launch(void* const* d_in, const int* in_sizes, int n_in,
                              void* d_out, int out_size) {
    const float* x    = (const float*)d_in[0];
    const void*  ei   = d_in[1];
    const float* Ws1  = (const float*)d_in[2];
    const float* bs1  = (const float*)d_in[3];
    const float* Wn1  = (const float*)d_in[4];
    const float* bn1  = (const float*)d_in[5];
    const float* Ws2  = (const float*)d_in[6];
    const float* bs2  = (const float*)d_in[7];
    const float* Wn2  = (const float*)d_in[8];
    const float* bn2  = (const float*)d_in[9];
    const float* Wout = (const float*)d_in[10];
    const float* bout = (const float*)d_in[11];

    int n = in_sizes[0] / 64;
    int e = in_sizes[1] / 2;

    float* out        = (float*)d_out;
    float* out_x32    = out;
    float* out_logits = out + (size_t)n * 32;

    int node_blocks    = (n + 7) / 8;           // 8 nodes (warps) per 256-thread block
    int scatter_blocks = (e * 8 + 255) / 256;   // 8 threads per edge

    detect_kernel<<<1, 32>>>((const long long*)ei, n, e);
    proj1_kernel<<<node_blocks, 256>>>(x, Ws1, bs1, Wn1, n);
    scatter_kernel<true><<<scatter_blocks, 256>>>(ei, e);
    inv_kernel<<<(n + 255) / 256, 256>>>(n);
    combine1_kernel<<<node_blocks, 256>>>(Ws2, bs2, Wn2, bn1, n);
    scatter_kernel<false><<<scatter_blocks, 256>>>(ei, e);
    combine2_kernel<<<node_blocks, 256>>>(Wout, bout, bn2, n, out_x32, out_logits);
}

// round 2
// speedup vs baseline: 1.1839x; 1.1839x over previous
#include <cuda_runtime.h>
#include <cuda_bf16.h>

#define NMAX 100000
#define EMAX 1600000
#define NBLK 391                 // ceil(NMAX/256)

// Scratch (zero-initialized at module load; scan_c re-zeroes g_deg each replay)
__device__ float g_selfA[NMAX * 32];
__device__ float g_projA[NMAX * 32];
__device__ float g_selfB[NMAX * 32];
__device__ float g_projB[NMAX * 32];
__device__ float g_inv[NMAX];
__device__ unsigned int g_deg[NMAX];
__device__ int   g_start[NMAX];    // CSR row start
__device__ int   g_fill[NMAX];     // fill cursor; after fill == row end
__device__ int   g_csr[EMAX];      // src ids grouped by dst
__device__ int   g_bsum[512];      // per-block degree sums
__device__ int   g_bpre[512];      // exclusive prefix of block sums
__device__ int   g_is32;           // edge_index dtype flag

// ---------------------------------------------------------------------------
// dtype detect: int64 edge_index interpreted as int64 stays in [0,n);
// int32 data reinterpreted as int64 overflows w.h.p. within 64 samples.
// ---------------------------------------------------------------------------
__global__ void detect_kernel(const long long* __restrict__ ei, int n, int e) {
    if (threadIdx.x == 0) {
        int is32 = 0;
        int m = e < 64 ? e : 64;
        for (int i = 0; i < m; i++) {
            long long v = ei[i];
            if (v < 0 || v >= (long long)n) { is32 = 1; break; }
        }
        g_is32 = is32;
    }
}

__device__ __forceinline__ int load_idx(const void* ei, long long elem) {
    if (g_is32) return ((const int*)ei)[elem];
    return (int)((const long long*)ei)[elem];
}

// ---------------------------------------------------------------------------
// CSR build: count -> scan (3 phases) -> fill
// ---------------------------------------------------------------------------
__global__ void count_kernel(const void* __restrict__ ei, int e) {
    int i = blockIdx.x * blockDim.x + threadIdx.x;
    if (i >= e) return;
    int d = load_idx(ei, (long long)e + i);
    atomicAdd(&g_deg[d], 1u);
}

__global__ void scan_a_kernel(int n) {
    __shared__ int s[8];
    int i = blockIdx.x * 256 + threadIdx.x;
    int v = (i < n) ? (int)g_deg[i] : 0;
#pragma unroll
    for (int o = 16; o > 0; o >>= 1) v += __shfl_down_sync(0xffffffffu, v, o);
    if ((threadIdx.x & 31) == 0) s[threadIdx.x >> 5] = v;
    __syncthreads();
    if (threadIdx.x == 0) {
        int t = 0;
#pragma unroll
        for (int w = 0; w < 8; w++) t += s[w];
        g_bsum[blockIdx.x] = t;
    }
}

__global__ void scan_b_kernel(int nb) {
    __shared__ int s[512];
    int tid = threadIdx.x;
    int v = (tid < nb) ? g_bsum[tid] : 0;
    s[tid] = v;
    __syncthreads();
#pragma unroll
    for (int off = 1; off < 512; off <<= 1) {
        int t = (tid >= off) ? s[tid - off] : 0;
        __syncthreads();
        s[tid] += t;
        __syncthreads();
    }
    if (tid < nb) g_bpre[tid] = s[tid] - v;   // exclusive
}

__global__ void scan_c_kernel(int n) {
    __shared__ int s[256];
    int tid = threadIdx.x;
    int i = blockIdx.x * 256 + tid;
    int v = (i < n) ? (int)g_deg[i] : 0;
    s[tid] = v;
    __syncthreads();
#pragma unroll
    for (int off = 1; off < 256; off <<= 1) {
        int t = (tid >= off) ? s[tid - off] : 0;
        __syncthreads();
        s[tid] += t;
        __syncthreads();
    }
    if (i < n) {
        int start = g_bpre[blockIdx.x] + s[tid] - v;  // global exclusive prefix
        g_start[i] = start;
        g_fill[i]  = start;
        g_inv[i]   = 1.0f / (float)(v > 1 ? v : 1);
        g_deg[i]   = 0u;                               // replay invariant
    }
}

__global__ void fill_kernel(const void* __restrict__ ei, int e) {
    int i = blockIdx.x * blockDim.x + threadIdx.x;
    if (i >= e) return;
    int s = load_idx(ei, i);
    int d = load_idx(ei, (long long)e + i);
    int pos = atomicAdd(&g_fill[d], 1);
    g_csr[pos] = s;
}

// ---------------------------------------------------------------------------
// proj1: g_selfA = x @ W_self1 + b_self1 ; g_projA = x @ W_neigh1
// warp-per-node; weights in SMEM; x row in 2 regs + shfl broadcast.
// ---------------------------------------------------------------------------
__global__ void proj1_kernel(const float* __restrict__ x,
                             const float* __restrict__ Ws,
                             const float* __restrict__ bs,
                             const float* __restrict__ Wn, int n) {
    __shared__ float sWs[64 * 32], sWn[64 * 32], sbs[32];
    for (int i = threadIdx.x; i < 64 * 32; i += 256) { sWs[i] = Ws[i]; sWn[i] = Wn[i]; }
    if (threadIdx.x < 32) sbs[threadIdx.x] = bs[threadIdx.x];
    __syncthreads();

    int warp = threadIdx.x >> 5, lane = threadIdx.x & 31;
    int node = blockIdx.x * 8 + warp;
    if (node >= n) return;

    float xv0 = x[(size_t)node * 64 + lane];
    float xv1 = x[(size_t)node * 64 + 32 + lane];
    float accs = sbs[lane], accn = 0.f;
#pragma unroll
    for (int k = 0; k < 32; k++) {
        float xk = __shfl_sync(0xffffffffu, xv0, k);
        accs = fmaf(xk, sWs[k * 32 + lane], accs);
        accn = fmaf(xk, sWn[k * 32 + lane], accn);
    }
#pragma unroll
    for (int k = 0; k < 32; k++) {
        float xk = __shfl_sync(0xffffffffu, xv1, k);
        accs = fmaf(xk, sWs[(32 + k) * 32 + lane], accs);
        accn = fmaf(xk, sWn[(32 + k) * 32 + lane], accn);
    }
    g_selfA[(size_t)node * 32 + lane] = accs;
    g_projA[(size_t)node * 32 + lane] = accn;
}

// ---------------------------------------------------------------------------
// Gather-sum over CSR neighbors: lane = feature, 128B coalesced row per iter.
// Neighbor ids prefetched coalesced then shfl-broadcast.
// ---------------------------------------------------------------------------
__device__ __forceinline__ float gather_sum(const float* __restrict__ proj,
                                            int node, int lane) {
    int start = g_start[node];
    int end   = g_fill[node];
    float acc = 0.f;
    for (int base = start; base < end; base += 32) {
        int rem  = end - base;
        int m    = rem < 32 ? rem : 32;
        int myid = (lane < m) ? g_csr[base + lane] : 0;
        for (int k = 0; k < m; k++) {
            int sidx = __shfl_sync(0xffffffffu, myid, k);
            acc += proj[(size_t)sidx * 32 + lane];
        }
    }
    return acc;
}

// ---------------------------------------------------------------------------
// agg1: h1 = relu(mean(neigh projA) + b_neigh1 + selfA);
//       g_selfB = h1 @ W_self2 + b_self2 ; g_projB = h1 @ W_neigh2
// ---------------------------------------------------------------------------
__global__ void agg_combine1_kernel(const float* __restrict__ Ws2,
                                    const float* __restrict__ bs2,
                                    const float* __restrict__ Wn2,
                                    const float* __restrict__ bn1, int n) {
    __shared__ float sWs[32 * 32], sWn[32 * 32], sbs[32], sbn[32];
    for (int i = threadIdx.x; i < 1024; i += 256) { sWs[i] = Ws2[i]; sWn[i] = Wn2[i]; }
    if (threadIdx.x < 32) { sbs[threadIdx.x] = bs2[threadIdx.x]; sbn[threadIdx.x] = bn1[threadIdx.x]; }
    __syncthreads();

    int warp = threadIdx.x >> 5, lane = threadIdx.x & 31;
    int node = blockIdx.x * 8 + warp;
    if (node >= n) return;

    size_t off = (size_t)node * 32 + lane;
    float acc = gather_sum(g_projA, node, lane);
    float h = fmaxf(fmaf(acc, g_inv[node], sbn[lane] + g_selfA[off]), 0.f);

    float accs = sbs[lane], accn = 0.f;
#pragma unroll
    for (int k = 0; k < 32; k++) {
        float hk = __shfl_sync(0xffffffffu, h, k);
        accs = fmaf(hk, sWs[k * 32 + lane], accs);
        accn = fmaf(hk, sWn[k * 32 + lane], accn);
    }
    g_selfB[off] = accs;
    g_projB[off] = accn;
}

// ---------------------------------------------------------------------------
// agg2: h2 = relu(mean(neigh projB) + b_neigh2 + selfB);
//       x32 = h2 ; logits = h2 @ W_out + b_out
// ---------------------------------------------------------------------------
__global__ void agg_combine2_kernel(const float* __restrict__ Wout,
                                    const float* __restrict__ bout,
                                    const float* __restrict__ bn2, int n,
                                    float* __restrict__ out_x32,
                                    float* __restrict__ out_logits) {
    __shared__ float sW[32 * 40], sb[40], sbn[32];
    for (int i = threadIdx.x; i < 1280; i += 256) sW[i] = Wout[i];
    if (threadIdx.x < 40) sb[threadIdx.x] = bout[threadIdx.x];
    if (threadIdx.x < 32) sbn[threadIdx.x] = bn2[threadIdx.x];
    __syncthreads();

    int warp = threadIdx.x >> 5, lane = threadIdx.x & 31;
    int node = blockIdx.x * 8 + warp;
    if (node >= n) return;

    size_t off = (size_t)node * 32 + lane;
    float acc = gather_sum(g_projB, node, lane);
    float h = fmaxf(fmaf(acc, g_inv[node], sbn[lane] + g_selfB[off]), 0.f);
    out_x32[off] = h;

    float acc0 = sb[lane];
    float acc1 = (lane < 8) ? sb[32 + lane] : 0.f;
#pragma unroll
    for (int k = 0; k < 32; k++) {
        float hk = __shfl_sync(0xffffffffu, h, k);
        acc0 = fmaf(hk, sW[k * 40 + lane], acc0);
        acc1 = fmaf(hk, sW[k * 40 + 32 + (lane & 7)], acc1);
    }
    out_logits[(size_t)node * 40 + lane] = acc0;
    if (lane < 8) out_logits[(size_t)node * 40 + 32 + lane] = acc1;
}

// ---------------------------------------------------------------------------
// Launch. Inputs: x, edge_index, W_self1, b_self1, W_neigh1, b_neigh1,
// W_self2, b_self2, W_neigh2, b_neigh2, W_out, b_out, W_lin1, b_lin1.
// Output: concat(x32 [N,32], logits [N,40]) fp32. W_lin1 path is dead code.
// ---------------------------------------------------------------------------
extern "C" void kernel_launch(void* const* d_in, const int* in_sizes, int n_in,
                              void* d_out, int out_size) {
    const float* x    = (const float*)d_in[0];
    const void*  ei   = d_in[1];
    const float* Ws1  = (const float*)d_in[2];
    const float* bs1  = (const float*)d_in[3];
    const float* Wn1  = (const float*)d_in[4];
    const float* bn1  = (const float*)d_in[5];
    const float* Ws2  = (const float*)d_in[6];
    const float* bs2  = (const float*)d_in[7];
    const float* Wn2  = (const float*)d_in[8];
    const float* bn2  = (const float*)d_in[9];
    const float* Wout = (const float*)d_in[10];
    const float* bout = (const float*)d_in[11];

    int n = in_sizes[0] / 64;
    int e = in_sizes[1] / 2;

    float* out        = (float*)d_out;
    float* out_x32    = out;
    float* out_logits = out + (size_t)n * 32;

    int node_blocks = (n + 7) / 8;        // 8 warps/block, warp per node
    int scan_blocks = (n + 255) / 256;
    int edge_blocks = (e + 255) / 256;

    detect_kernel<<<1, 32>>>((const long long*)ei, n, e);
    count_kernel<<<edge_blocks, 256>>>(ei, e);
    scan_a_kernel<<<scan_blocks, 256>>>(n);
    scan_b_kernel<<<1, 512>>>(scan_blocks);
    scan_c_kernel<<<scan_blocks, 256>>>(n);
    fill_kernel<<<edge_blocks, 256>>>(ei, e);
    proj1_kernel<<<node_blocks, 256>>>(x, Ws1, bs1, Wn1, n);
    agg_combine1_kernel<<<node_blocks, 256>>>(Ws2, bs2, Wn2, bn1, n);
    agg_combine2_kernel<<<node_blocks, 256>>>(Wout, bout, bn2, n, out_x32, out_logits);
}

// round 3
// speedup vs baseline: 1.2328x; 1.0413x over previous
#include <cuda_runtime.h>
#include <cuda_bf16.h>

#define NMAX 100000
#define EMAX 1600000

typedef unsigned long long u64;

// Scratch (zero-init at load; offset_kernel re-zeroes g_deg, detect re-zeroes g_total)
__device__ float4 g_selfA[NMAX * 8];
__device__ float4 g_projA[NMAX * 8];
__device__ float4 g_selfB[NMAX * 8];
__device__ float4 g_projB[NMAX * 8];
__device__ float  g_inv[NMAX];
__device__ unsigned int g_deg[NMAX];
__device__ int    g_start[NMAX];
__device__ int    g_fill[NMAX];     // after fill_kernel: row end
__device__ int    g_csr[EMAX];
__device__ int    g_total;
__device__ int    g_is32;

// ---- packed fp32x2 helpers (Blackwell FFMA2 pipe, PTX-only) ----
__device__ __forceinline__ u64 pack2(float x, float y) {
    u64 r; asm("mov.b64 %0, {%1,%2};" : "=l"(r) : "f"(x), "f"(y)); return r;
}
__device__ __forceinline__ void unpack2(u64 v, float& x, float& y) {
    asm("mov.b64 {%0,%1}, %2;" : "=f"(x), "=f"(y) : "l"(v));
}
__device__ __forceinline__ void fma2(u64& d, u64 a, u64 b) {
    asm("fma.rn.f32x2 %0, %1, %2, %0;" : "+l"(d) : "l"(a), "l"(b));
}

// ---------------------------------------------------------------------------
// detect dtype (parallel ballot) + reset g_total for this replay.
// int32 data reinterpreted as int64 lands outside [0,n) w.h.p.
// ---------------------------------------------------------------------------
__global__ void detect_kernel(const long long* __restrict__ ei, int n) {
    long long v = ei[threadIdx.x];
    int bad = (v < 0 || v >= (long long)n) ? 1 : 0;
    unsigned b = __ballot_sync(0xffffffffu, bad);
    if (threadIdx.x == 0) { g_is32 = b ? 1 : 0; g_total = 0; }
}

__device__ __forceinline__ int load_idx(const void* ei, long long elem) {
    if (g_is32) return ((const int*)ei)[elem];
    return (int)((const long long*)ei)[elem];
}

// ---------------------------------------------------------------------------
// count: degree histogram (RED, no return value)
// ---------------------------------------------------------------------------
__global__ void count_kernel(const void* __restrict__ ei, int e) {
    int i = blockIdx.x * blockDim.x + threadIdx.x;
    if (i >= e) return;
    int d = load_idx(ei, (long long)e + i);
    atomicAdd(&g_deg[d], 1u);
}

// ---------------------------------------------------------------------------
// offset: CSR row ranges via warp prefix + one global atomic per warp.
// Row order across warps is arbitrary (disjoint ranges suffice).
// Also computes 1/max(deg,1) and resets g_deg (replay invariant).
// ---------------------------------------------------------------------------
__global__ void offset_kernel(int n) {
    int i = blockIdx.x * 256 + threadIdx.x;
    int lane = threadIdx.x & 31;
    int deg = (i < n) ? (int)g_deg[i] : 0;
    int pre = deg;
#pragma unroll
    for (int o = 1; o < 32; o <<= 1) {
        int t = __shfl_up_sync(0xffffffffu, pre, o);
        if (lane >= o) pre += t;
    }
    int wsum = __shfl_sync(0xffffffffu, pre, 31);
    int base = 0;
    if (lane == 31) base = atomicAdd(&g_total, wsum);
    base = __shfl_sync(0xffffffffu, base, 31);
    if (i < n) {
        int start = base + pre - deg;
        g_start[i] = start;
        g_fill[i]  = start;
        g_inv[i]   = 1.0f / (float)(deg > 1 ? deg : 1);
        g_deg[i]   = 0u;
    }
}

__global__ void fill_kernel(const void* __restrict__ ei, int e) {
    int i = blockIdx.x * blockDim.x + threadIdx.x;
    if (i >= e) return;
    int s = load_idx(ei, i);
    int d = load_idx(ei, (long long)e + i);
    int pos = atomicAdd(&g_fill[d], 1);
    g_csr[pos] = s;
}

// ---------------------------------------------------------------------------
// proj1: selfA = x@W_self1+b_self1 ; projA = x@W_neigh1  (one FFMA2 per k)
// ---------------------------------------------------------------------------
__global__ void proj1_kernel(const float* __restrict__ x,
                             const float* __restrict__ Ws,
                             const float* __restrict__ bs,
                             const float* __restrict__ Wn, int n) {
    __shared__ float2 sW2[64 * 32];
    __shared__ float  sbs[32];
    for (int i = threadIdx.x; i < 64 * 32; i += 256)
        sW2[i] = make_float2(Ws[i], Wn[i]);
    if (threadIdx.x < 32) sbs[threadIdx.x] = bs[threadIdx.x];
    __syncthreads();

    int warp = threadIdx.x >> 5, lane = threadIdx.x & 31;
    int node = blockIdx.x * 8 + warp;
    if (node >= n) return;

    float xv0 = x[(size_t)node * 64 + lane];
    float xv1 = x[(size_t)node * 64 + 32 + lane];
    u64 acc2 = pack2(sbs[lane], 0.f);
#pragma unroll
    for (int k = 0; k < 32; k++) {
        float xk = __shfl_sync(0xffffffffu, xv0, k);
        float2 w = sW2[k * 32 + lane];
        fma2(acc2, pack2(w.x, w.y), pack2(xk, xk));
    }
#pragma unroll
    for (int k = 0; k < 32; k++) {
        float xk = __shfl_sync(0xffffffffu, xv1, k);
        float2 w = sW2[(32 + k) * 32 + lane];
        fma2(acc2, pack2(w.x, w.y), pack2(xk, xk));
    }
    float accs, accn; unpack2(acc2, accs, accn);
    ((float*)g_selfA)[(size_t)node * 32 + lane] = accs;
    ((float*)g_projA)[(size_t)node * 32 + lane] = accn;
}

// ---------------------------------------------------------------------------
// gather: 4 neighbors per warp-iteration (8 lanes x float4 each).
// Returns float4 of features (lane&7)*4..+3, replicated across lane>>3.
// ---------------------------------------------------------------------------
__device__ __forceinline__ float4 gather_sum4(const float4* __restrict__ proj4,
                                              int node, int lane) {
    int start = g_start[node], end = g_fill[node];
    int sub = lane >> 3, fl = lane & 7;
    float4 acc = make_float4(0.f, 0.f, 0.f, 0.f);
    for (int base = start; base < end; base += 32) {
        int rem = end - base;
        int m = rem < 32 ? rem : 32;
        int myid = (lane < m) ? g_csr[base + lane] : 0;
#pragma unroll 2
        for (int k = 0; k < m; k += 4) {
            int g = k + sub;  // always < 32
            int sid = __shfl_sync(0xffffffffu, myid, g);
            if (g < m) {
                float4 v = proj4[(size_t)sid * 8 + fl];
                acc.x += v.x; acc.y += v.y; acc.z += v.z; acc.w += v.w;
            }
        }
    }
#pragma unroll
    for (int o = 8; o <= 16; o <<= 1) {
        acc.x += __shfl_xor_sync(0xffffffffu, acc.x, o);
        acc.y += __shfl_xor_sync(0xffffffffu, acc.y, o);
        acc.z += __shfl_xor_sync(0xffffffffu, acc.z, o);
        acc.w += __shfl_xor_sync(0xffffffffu, acc.w, o);
    }
    return acc;
}

// ---------------------------------------------------------------------------
// agg1: h1 = relu(mean(neigh projA)+b_neigh1+selfA);
//       selfB = h1@W_self2+b_self2 ; projB = h1@W_neigh2   (FFMA2)
// ---------------------------------------------------------------------------
__global__ void agg_combine1_kernel(const float* __restrict__ Ws2,
                                    const float* __restrict__ bs2,
                                    const float* __restrict__ Wn2,
                                    const float* __restrict__ bn1, int n) {
    __shared__ float2 sW2[32 * 32];
    __shared__ float  sbs[32];
    __shared__ float4 sbn4[8];
    __shared__ float4 sh4[8 * 8];   // h staging, 8 warps x 32 floats
    for (int i = threadIdx.x; i < 1024; i += 256)
        sW2[i] = make_float2(Ws2[i], Wn2[i]);
    if (threadIdx.x < 32) sbs[threadIdx.x] = bs2[threadIdx.x];
    if (threadIdx.x < 8) sbn4[threadIdx.x] = ((const float4*)bn1)[threadIdx.x];
    __syncthreads();

    int warp = threadIdx.x >> 5, lane = threadIdx.x & 31;
    int node = blockIdx.x * 8 + warp;
    if (node >= n) return;
    int sub = lane >> 3, fl = lane & 7;

    float4 acc = gather_sum4(g_projA, node, lane);
    float inv = g_inv[node];
    float4 s4 = g_selfA[(size_t)node * 8 + fl];
    float4 b4 = sbn4[fl];
    float4 h4;
    h4.x = fmaxf(fmaf(acc.x, inv, b4.x + s4.x), 0.f);
    h4.y = fmaxf(fmaf(acc.y, inv, b4.y + s4.y), 0.f);
    h4.z = fmaxf(fmaf(acc.z, inv, b4.z + s4.z), 0.f);
    h4.w = fmaxf(fmaf(acc.w, inv, b4.w + s4.w), 0.f);
    if (sub == 0) sh4[warp * 8 + fl] = h4;
    __syncwarp();
    float h = ((const float*)sh4)[warp * 32 + lane];

    u64 acc2 = pack2(sbs[lane], 0.f);
#pragma unroll
    for (int k = 0; k < 32; k++) {
        float hk = __shfl_sync(0xffffffffu, h, k);
        float2 w = sW2[k * 32 + lane];
        fma2(acc2, pack2(w.x, w.y), pack2(hk, hk));
    }
    float accs, accn; unpack2(acc2, accs, accn);
    ((float*)g_selfB)[(size_t)node * 32 + lane] = accs;
    ((float*)g_projB)[(size_t)node * 32 + lane] = accn;
}

// ---------------------------------------------------------------------------
// agg2: h2 = relu(mean(neigh projB)+b_neigh2+selfB);
//       x32 = h2 ; logits = h2@W_out+b_out   (FFMA2 pairs the two 40-col halves)
// ---------------------------------------------------------------------------
__global__ void agg_combine2_kernel(const float* __restrict__ Wout,
                                    const float* __restrict__ bout,
                                    const float* __restrict__ bn2, int n,
                                    float* __restrict__ out_x32,
                                    float* __restrict__ out_logits) {
    __shared__ float2 sW2[32 * 32];
    __shared__ float  sb[40];
    __shared__ float4 sbn4[8];
    __shared__ float4 sh4[8 * 8];
    for (int i = threadIdx.x; i < 1024; i += 256) {
        int k = i >> 5, l = i & 31;
        sW2[i] = make_float2(Wout[k * 40 + l], Wout[k * 40 + 32 + (l & 7)]);
    }
    if (threadIdx.x < 40) sb[threadIdx.x] = bout[threadIdx.x];
    if (threadIdx.x < 8) sbn4[threadIdx.x] = ((const float4*)bn2)[threadIdx.x];
    __syncthreads();

    int warp = threadIdx.x >> 5, lane = threadIdx.x & 31;
    int node = blockIdx.x * 8 + warp;
    if (node >= n) return;
    int sub = lane >> 3, fl = lane & 7;

    float4 acc = gather_sum4(g_projB, node, lane);
    float inv = g_inv[node];
    float4 s4 = g_selfB[(size_t)node * 8 + fl];
    float4 b4 = sbn4[fl];
    float4 h4;
    h4.x = fmaxf(fmaf(acc.x, inv, b4.x + s4.x), 0.f);
    h4.y = fmaxf(fmaf(acc.y, inv, b4.y + s4.y), 0.f);
    h4.z = fmaxf(fmaf(acc.z, inv, b4.z + s4.z), 0.f);
    h4.w = fmaxf(fmaf(acc.w, inv, b4.w + s4.w), 0.f);
    if (sub == 0) {
        ((float4*)out_x32)[(size_t)node * 8 + fl] = h4;
        sh4[warp * 8 + fl] = h4;
    }
    __syncwarp();
    float h = ((const float*)sh4)[warp * 32 + lane];

    u64 acc2 = pack2(sb[lane], (lane < 8) ? sb[32 + lane] : 0.f);
#pragma unroll
    for (int k = 0; k < 32; k++) {
        float hk = __shfl_sync(0xffffffffu, h, k);
        float2 w = sW2[k * 32 + lane];
        fma2(acc2, pack2(w.x, w.y), pack2(hk, hk));
    }
    float acc0, acc1; unpack2(acc2, acc0, acc1);
    out_logits[(size_t)node * 40 + lane] = acc0;
    if (lane < 8) out_logits[(size_t)node * 40 + 32 + lane] = acc1;
}

// ---------------------------------------------------------------------------
// Launch. Output: concat(x32 [N,32], logits [N,40]) fp32. W_lin1 is dead code.
// ---------------------------------------------------------------------------
extern "C" void kernel_launch(void* const* d_in, const int* in_sizes, int n_in,
                              void* d_out, int out_size) {
    const float* x    = (const float*)d_in[0];
    const void*  ei   = d_in[1];
    const float* Ws1  = (const float*)d_in[2];
    const float* bs1  = (const float*)d_in[3];
    const float* Wn1  = (const float*)d_in[4];
    const float* bn1  = (const float*)d_in[5];
    const float* Ws2  = (const float*)d_in[6];
    const float* bs2  = (const float*)d_in[7];
    const float* Wn2  = (const float*)d_in[8];
    const float* bn2  = (const float*)d_in[9];
    const float* Wout = (const float*)d_in[10];
    const float* bout = (const float*)d_in[11];

    int n = in_sizes[0] / 64;
    int e = in_sizes[1] / 2;

    float* out        = (float*)d_out;
    float* out_x32    = out;
    float* out_logits = out + (size_t)n * 32;

    int node_blocks = (n + 7) / 8;
    int nb256       = (n + 255) / 256;
    int eb256       = (e + 255) / 256;

    detect_kernel<<<1, 32>>>((const long long*)ei, n);
    count_kernel<<<eb256, 256>>>(ei, e);
    offset_kernel<<<nb256, 256>>>(n);
    fill_kernel<<<eb256, 256>>>(ei, e);
    proj1_kernel<<<node_blocks, 256>>>(x, Ws1, bs1, Wn1, n);
    agg_combine1_kernel<<<node_blocks, 256>>>(Ws2, bs2, Wn2, bn1, n);
    agg_combine2_kernel<<<node_blocks, 256>>>(Wout, bout, bn2, n, out_x32, out_logits);
}

// round 4
// speedup vs baseline: 1.6681x; 1.3531x over previous
#include <cuda_runtime.h>
#include <cuda_bf16.h>

#define NMAX 100000
#define EMAX 1600000

typedef unsigned long long u64;

// Scratch (zero-init at load; offset_kernel re-zeroes g_deg, detect re-zeroes g_total)
__device__ float4 g_selfA[NMAX * 8];
__device__ float4 g_projA[NMAX * 8];
__device__ float4 g_selfB[NMAX * 8];
__device__ float4 g_projB[NMAX * 8];
__device__ float  g_inv[NMAX];
__device__ unsigned int g_deg[NMAX];
__device__ int    g_start[NMAX];
__device__ int    g_fill[NMAX];     // after fill_kernel: row end
__device__ int    g_csr[EMAX];
__device__ int    g_total;
__device__ int    g_is32;

// ---- packed fp32x2 helpers (Blackwell FFMA2 pipe, PTX-only) ----
__device__ __forceinline__ u64 pack2(float x, float y) {
    u64 r; asm("mov.b64 %0, {%1,%2};" : "=l"(r) : "f"(x), "f"(y)); return r;
}
__device__ __forceinline__ void unpack2(u64 v, float& x, float& y) {
    asm("mov.b64 {%0,%1}, %2;" : "=f"(x), "=f"(y) : "l"(v));
}
__device__ __forceinline__ void fma2(u64& d, u64 a, u64 b) {
    asm("fma.rn.f32x2 %0, %1, %2, %0;" : "+l"(d) : "l"(a), "l"(b));
}

// ---------------------------------------------------------------------------
// dtype detect (ballot) + reset g_total for this replay.
// ---------------------------------------------------------------------------
__global__ void detect_kernel(const long long* __restrict__ ei, int n) {
    long long v = ei[threadIdx.x];
    int bad = (v < 0 || v >= (long long)n) ? 1 : 0;
    unsigned b = __ballot_sync(0xffffffffu, bad);
    if (threadIdx.x == 0) { g_is32 = b ? 1 : 0; g_total = 0; }
}

__device__ __forceinline__ int load_idx(const void* ei, long long elem) {
    if (g_is32) return ((const int*)ei)[elem];
    return (int)((const long long*)ei)[elem];
}

// ---------------------------------------------------------------------------
// CSR build: count -> offset (warp prefix + global atomic) -> fill
// ---------------------------------------------------------------------------
__global__ void count_kernel(const void* __restrict__ ei, int e) {
    int i = blockIdx.x * blockDim.x + threadIdx.x;
    if (i >= e) return;
    int d = load_idx(ei, (long long)e + i);
    atomicAdd(&g_deg[d], 1u);
}

__global__ void offset_kernel(int n) {
    int i = blockIdx.x * 256 + threadIdx.x;
    int lane = threadIdx.x & 31;
    int deg = (i < n) ? (int)g_deg[i] : 0;
    int pre = deg;
#pragma unroll
    for (int o = 1; o < 32; o <<= 1) {
        int t = __shfl_up_sync(0xffffffffu, pre, o);
        if (lane >= o) pre += t;
    }
    int wsum = __shfl_sync(0xffffffffu, pre, 31);
    int base = 0;
    if (lane == 31) base = atomicAdd(&g_total, wsum);
    base = __shfl_sync(0xffffffffu, base, 31);
    if (i < n) {
        int start = base + pre - deg;
        g_start[i] = start;
        g_fill[i]  = start;
        g_inv[i]   = 1.0f / (float)(deg > 1 ? deg : 1);
        g_deg[i]   = 0u;
    }
}

__global__ void fill_kernel(const void* __restrict__ ei, int e) {
    int i = blockIdx.x * blockDim.x + threadIdx.x;
    if (i >= e) return;
    int s = load_idx(ei, i);
    int d = load_idx(ei, (long long)e + i);
    int pos = atomicAdd(&g_fill[d], 1);
    g_csr[pos] = s;
}

// ---------------------------------------------------------------------------
// proj1: selfA = x@W_self1+b_self1 ; projA = x@W_neigh1
// 4 nodes per warp: per k, ONE LDS.64 weight read amortized over 4 FFMA2.
// ---------------------------------------------------------------------------
__global__ void proj1_kernel(const float* __restrict__ x,
                             const float* __restrict__ Ws,
                             const float* __restrict__ bs,
                             const float* __restrict__ Wn, int n) {
    __shared__ float2 sW2[64 * 32];
    __shared__ float  sbs[32];
    for (int i = threadIdx.x; i < 64 * 32; i += 256)
        sW2[i] = make_float2(Ws[i], Wn[i]);
    if (threadIdx.x < 32) sbs[threadIdx.x] = bs[threadIdx.x];
    __syncthreads();

    int warp = threadIdx.x >> 5, lane = threadIdx.x & 31;
    int node0 = (blockIdx.x * 8 + warp) * 4;
    if (node0 >= n) return;

    float xv0[4], xv1[4];
    u64 acc2[4];
#pragma unroll
    for (int i = 0; i < 4; i++) {
        int node = node0 + i;
        if (node < n) {
            xv0[i] = x[(size_t)node * 64 + lane];
            xv1[i] = x[(size_t)node * 64 + 32 + lane];
        } else { xv0[i] = 0.f; xv1[i] = 0.f; }
        acc2[i] = pack2(sbs[lane], 0.f);
    }
#pragma unroll
    for (int k = 0; k < 32; k++) {
        float2 w = sW2[k * 32 + lane];
        u64 wp = pack2(w.x, w.y);
#pragma unroll
        for (int i = 0; i < 4; i++) {
            float xk = __shfl_sync(0xffffffffu, xv0[i], k);
            fma2(acc2[i], wp, pack2(xk, xk));
        }
    }
#pragma unroll
    for (int k = 0; k < 32; k++) {
        float2 w = sW2[(32 + k) * 32 + lane];
        u64 wp = pack2(w.x, w.y);
#pragma unroll
        for (int i = 0; i < 4; i++) {
            float xk = __shfl_sync(0xffffffffu, xv1[i], k);
            fma2(acc2[i], wp, pack2(xk, xk));
        }
    }
#pragma unroll
    for (int i = 0; i < 4; i++) {
        int node = node0 + i;
        if (node < n) {
            float accs, accn; unpack2(acc2[i], accs, accn);
            ((float*)g_selfA)[(size_t)node * 32 + lane] = accs;
            ((float*)g_projA)[(size_t)node * 32 + lane] = accn;
        }
    }
}

// ---------------------------------------------------------------------------
// gather: 4 neighbors per warp-iteration (8 lanes x float4 each).
// Returns float4 of features (lane&7)*4..+3, replicated across lane>>3.
// ---------------------------------------------------------------------------
__device__ __forceinline__ float4 gather_sum4(const float4* __restrict__ proj4,
                                              int node, int lane) {
    int start = g_start[node], end = g_fill[node];
    int sub = lane >> 3, fl = lane & 7;
    float4 acc = make_float4(0.f, 0.f, 0.f, 0.f);
    for (int base = start; base < end; base += 32) {
        int rem = end - base;
        int m = rem < 32 ? rem : 32;
        int myid = (lane < m) ? g_csr[base + lane] : 0;
#pragma unroll 2
        for (int k = 0; k < m; k += 4) {
            int g = k + sub;  // always < 32
            int sid = __shfl_sync(0xffffffffu, myid, g);
            if (g < m) {
                float4 v = proj4[(size_t)sid * 8 + fl];
                acc.x += v.x; acc.y += v.y; acc.z += v.z; acc.w += v.w;
            }
        }
    }
#pragma unroll
    for (int o = 8; o <= 16; o <<= 1) {
        acc.x += __shfl_xor_sync(0xffffffffu, acc.x, o);
        acc.y += __shfl_xor_sync(0xffffffffu, acc.y, o);
        acc.z += __shfl_xor_sync(0xffffffffu, acc.z, o);
        acc.w += __shfl_xor_sync(0xffffffffu, acc.w, o);
    }
    return acc;
}

// ---------------------------------------------------------------------------
// Shared body: gather h for 4 nodes of this warp, stage to SMEM, reload
// as h[node][lane] regs. Returns via h_reg[4]; invalid nodes get garbage.
// ---------------------------------------------------------------------------
__device__ __forceinline__ void gather_h4(const float4* __restrict__ proj4,
                                          const float4* __restrict__ self4,
                                          const float4* __restrict__ bn4s,
                                          float4* __restrict__ stage,  // [4*8] this warp
                                          int node0, int n, int lane,
                                          float h_reg[4],
                                          float4* out_x32_4 /*nullable*/) {
    int sub = lane >> 3, fl = lane & 7;
#pragma unroll
    for (int i = 0; i < 4; i++) {
        int node = node0 + i;
        if (node >= n) continue;
        float4 acc = gather_sum4(proj4, node, lane);
        float inv = g_inv[node];
        float4 s4 = self4[(size_t)node * 8 + fl];
        float4 b4 = bn4s[fl];
        float4 h4;
        h4.x = fmaxf(fmaf(acc.x, inv, b4.x + s4.x), 0.f);
        h4.y = fmaxf(fmaf(acc.y, inv, b4.y + s4.y), 0.f);
        h4.z = fmaxf(fmaf(acc.z, inv, b4.z + s4.z), 0.f);
        h4.w = fmaxf(fmaf(acc.w, inv, b4.w + s4.w), 0.f);
        if (sub == 0) {
            stage[i * 8 + fl] = h4;
            if (out_x32_4) out_x32_4[(size_t)node * 8 + fl] = h4;
        }
    }
    __syncwarp();
#pragma unroll
    for (int i = 0; i < 4; i++)
        h_reg[i] = ((const float*)stage)[i * 32 + lane];
}

// ---------------------------------------------------------------------------
// agg1: h1 = relu(mean(neigh projA)+b_neigh1+selfA);
//       selfB = h1@W_self2+b_self2 ; projB = h1@W_neigh2   (4 nodes/warp)
// ---------------------------------------------------------------------------
__global__ void agg_combine1_kernel(const float* __restrict__ Ws2,
                                    const float* __restrict__ bs2,
                                    const float* __restrict__ Wn2,
                                    const float* __restrict__ bn1, int n) {
    __shared__ float2 sW2[32 * 32];
    __shared__ float  sbs[32];
    __shared__ float4 sbn4[8];
    __shared__ float4 sh4[8 * 4 * 8];   // 8 warps x 4 nodes x 32 floats
    for (int i = threadIdx.x; i < 1024; i += 256)
        sW2[i] = make_float2(Ws2[i], Wn2[i]);
    if (threadIdx.x < 32) sbs[threadIdx.x] = bs2[threadIdx.x];
    if (threadIdx.x < 8) sbn4[threadIdx.x] = ((const float4*)bn1)[threadIdx.x];
    __syncthreads();

    int warp = threadIdx.x >> 5, lane = threadIdx.x & 31;
    int node0 = (blockIdx.x * 8 + warp) * 4;
    if (node0 >= n) return;

    float h_reg[4];
    gather_h4(g_projA, g_selfA, sbn4, &sh4[warp * 32], node0, n, lane, h_reg, nullptr);

    u64 acc2[4];
#pragma unroll
    for (int i = 0; i < 4; i++) acc2[i] = pack2(sbs[lane], 0.f);
#pragma unroll
    for (int k = 0; k < 32; k++) {
        float2 w = sW2[k * 32 + lane];
        u64 wp = pack2(w.x, w.y);
#pragma unroll
        for (int i = 0; i < 4; i++) {
            float hk = __shfl_sync(0xffffffffu, h_reg[i], k);
            fma2(acc2[i], wp, pack2(hk, hk));
        }
    }
#pragma unroll
    for (int i = 0; i < 4; i++) {
        int node = node0 + i;
        if (node < n) {
            float accs, accn; unpack2(acc2[i], accs, accn);
            ((float*)g_selfB)[(size_t)node * 32 + lane] = accs;
            ((float*)g_projB)[(size_t)node * 32 + lane] = accn;
        }
    }
}

// ---------------------------------------------------------------------------
// agg2: h2 = relu(mean(neigh projB)+b_neigh2+selfB);
//       x32 = h2 ; logits = h2@W_out+b_out   (4 nodes/warp)
// ---------------------------------------------------------------------------
__global__ void agg_combine2_kernel(const float* __restrict__ Wout,
                                    const float* __restrict__ bout,
                                    const float* __restrict__ bn2, int n,
                                    float* __restrict__ out_x32,
                                    float* __restrict__ out_logits) {
    __shared__ float2 sW2[32 * 32];
    __shared__ float  sb[40];
    __shared__ float4 sbn4[8];
    __shared__ float4 sh4[8 * 4 * 8];
    for (int i = threadIdx.x; i < 1024; i += 256) {
        int k = i >> 5, l = i & 31;
        sW2[i] = make_float2(Wout[k * 40 + l], Wout[k * 40 + 32 + (l & 7)]);
    }
    if (threadIdx.x < 40) sb[threadIdx.x] = bout[threadIdx.x];
    if (threadIdx.x < 8) sbn4[threadIdx.x] = ((const float4*)bn2)[threadIdx.x];
    __syncthreads();

    int warp = threadIdx.x >> 5, lane = threadIdx.x & 31;
    int node0 = (blockIdx.x * 8 + warp) * 4;
    if (node0 >= n) return;

    float h_reg[4];
    gather_h4(g_projB, g_selfB, sbn4, &sh4[warp * 32], node0, n, lane, h_reg,
              (float4*)out_x32);

    u64 acc2[4];
#pragma unroll
    for (int i = 0; i < 4; i++)
        acc2[i] = pack2(sb[lane], (lane < 8) ? sb[32 + lane] : 0.f);
#pragma unroll
    for (int k = 0; k < 32; k++) {
        float2 w = sW2[k * 32 + lane];
        u64 wp = pack2(w.x, w.y);
#pragma unroll
        for (int i = 0; i < 4; i++) {
            float hk = __shfl_sync(0xffffffffu, h_reg[i], k);
            fma2(acc2[i], wp, pack2(hk, hk));
        }
    }
#pragma unroll
    for (int i = 0; i < 4; i++) {
        int node = node0 + i;
        if (node < n) {
            float a0, a1; unpack2(acc2[i], a0, a1);
            out_logits[(size_t)node * 40 + lane] = a0;
            if (lane < 8) out_logits[(size_t)node * 40 + 32 + lane] = a1;
        }
    }
}

// ---------------------------------------------------------------------------
// Launch. Output: concat(x32 [N,32], logits [N,40]) fp32. W_lin1 is dead code.
// ---------------------------------------------------------------------------
extern "C" void kernel_launch(void* const* d_in, const int* in_sizes, int n_in,
                              void* d_out, int out_size) {
    const float* x    = (const float*)d_in[0];
    const void*  ei   = d_in[1];
    const float* Ws1  = (const float*)d_in[2];
    const float* bs1  = (const float*)d_in[3];
    const float* Wn1  = (const float*)d_in[4];
    const float* bn1  = (const float*)d_in[5];
    const float* Ws2  = (const float*)d_in[6];
    const float* bs2  = (const float*)d_in[7];
    const float* Wn2  = (const float*)d_in[8];
    const float* bn2  = (const float*)d_in[9];
    const float* Wout = (const float*)d_in[10];
    const float* bout = (const float*)d_in[11];

    int n = in_sizes[0] / 64;
    int e = in_sizes[1] / 2;

    float* out        = (float*)d_out;
    float* out_x32    = out;
    float* out_logits = out + (size_t)n * 32;

    int node_blocks = (n + 31) / 32;   // 8 warps/block x 4 nodes/warp
    int nb256       = (n + 255) / 256;
    int eb256       = (e + 255) / 256;

    detect_kernel<<<1, 32>>>((const long long*)ei, n);
    count_kernel<<<eb256, 256>>>(ei, e);
    offset_kernel<<<nb256, 256>>>(n);
    fill_kernel<<<eb256, 256>>>(ei, e);
    proj1_kernel<<<node_blocks, 256>>>(x, Ws1, bs1, Wn1, n);
    agg_combine1_kernel<<<node_blocks, 256>>>(Ws2, bs2, Wn2, bn1, n);
    agg_combine2_kernel<<<node_blocks, 256>>>(Wout, bout, bn2, n, out_x32, out_logits);
}